// round 8
// baseline (speedup 1.0000x reference)
#include <cuda_runtime.h>
#include <cuda_bf16.h>

#define DIM 128
#define TEMP_INV (1.0f / 0.07f)
#define SLOTS 8   // ring slots per warp = 2 groups of 4 rows

__device__ __forceinline__ float dot4(float4 a, float4 b) {
    return a.x * b.x + a.y * b.y + a.z * b.z + a.w * b.w;
}

__global__ __launch_bounds__(256, 6)
void la_loss_kernel(const float* __restrict__ codes,
                    const float* __restrict__ bank,
                    const void* __restrict__ idx_bg,
                    const void* __restrict__ idx_cl,
                    float* __restrict__ out,
                    int K)
{
    // per-warp private ring: 8 warps x 8 slots x 512B = 32KB
    __shared__ float4 buf[8][SLOTS][32];
    __shared__ float s[8];

    const int b    = blockIdx.x;
    const int tid  = threadIdx.x;
    const int wid  = tid >> 5;      // 0..7
    const int lane = tid & 31;
    const int pos  = lane & 7;      // chunk position within a row (8 lanes/row)
    const int rsub = lane >> 3;     // which of the 4 rows in a consume-group

    // warps 0-3 -> background indices, warps 4-7 -> close indices
    const void* idx = (wid < 4) ? idx_bg : idx_cl;

    // ---- per-warp inline index-dtype detection (values < 2^20) ----
    const unsigned int* w = (const unsigned int*)idx;
    const bool is64 = __all_sync(0xffffffffu, w[2 * lane + 1] == 0u);

    // ---- v: lane holds chunks {pos+8j}, j=0..3 (each 8-lane group = full vec)
    const float4* __restrict__ codes4 = reinterpret_cast<const float4*>(codes);
    float4 v[4];
    float ss = 0.0f;
#pragma unroll
    for (int j = 0; j < 4; j++) {
        v[j] = codes4[(size_t)b * 32 + pos + 8 * j];
        ss += dot4(v[j], v[j]);
    }
#pragma unroll
    for (int o = 1; o < 8; o <<= 1) ss += __shfl_xor_sync(0xffffffffu, ss, o);
    const float rn = rsqrtf(ss);
#pragma unroll
    for (int j = 0; j < 4; j++) {
        v[j].x *= rn; v[j].y *= rn; v[j].z *= rn; v[j].w *= rn;
    }

    const int wsub = wid & 3;
    const size_t base = (size_t)b * (size_t)K;
    const int F = (K - wsub + 3) >> 2;     // rows this warp owns (50 for K=200)

    // fill row f into ring slot; empty commit keeps group accounting uniform
    auto fill = [&](int f, int slot) {
        if (f < F) {
            int m = wsub + 4 * f;
            long long ii;
            if (is64) ii = reinterpret_cast<const long long*>(idx)[base + m];
            else      ii = (long long)reinterpret_cast<const int*>(idx)[base + m];
            const float4* src = reinterpret_cast<const float4*>(bank + (size_t)ii * DIM) + lane;
            unsigned sad = (unsigned)__cvta_generic_to_shared(&buf[wid][slot][lane]);
            asm volatile("cp.async.cg.shared.global [%0], [%1], 16;\n"
                         :: "r"(sad), "l"(src));
        }
        asm volatile("cp.async.commit_group;\n");
    };

    // prologue: fill all 8 slots (rows f=0..7, 8 pending groups)
#pragma unroll
    for (int k = 0; k < SLOTS; k++) fill(k, k);

    float acc = 0.0f;
    const int P = (F + 3) >> 2;            // 4-row iterations (13 for F=50)
    for (int p = 0; p < P; p++) {
        // retire the oldest 4 groups -> this iteration's 4 rows are complete
        asm volatile("cp.async.wait_group 4;\n");
        __syncwarp();

        const int sbase = (p & 1) * 4;
        const int slot  = sbase + rsub;    // this lane's row
        // strided chunks pos, pos+8, pos+16, pos+24: conflict-free LDS.128
        float4 r0 = buf[wid][slot][pos];
        float4 r1 = buf[wid][slot][pos + 8];
        float4 r2 = buf[wid][slot][pos + 16];
        float4 r3 = buf[wid][slot][pos + 24];

        // refill the 4 consumed slots with rows for iteration p+2
#pragma unroll
        for (int k = 0; k < 4; k++) fill(4 * (p + 2) + k, sbase + k);

        float d = dot4(r0, v[0]) + dot4(r1, v[1]) + dot4(r2, v[2]) + dot4(r3, v[3]);
        // 3-step butterfly within each 8-lane group -> per-row sum
#pragma unroll
        for (int o = 1; o < 8; o <<= 1) d += __shfl_xor_sync(0xffffffffu, d, o);
        if (4 * p + rsub < F && pos == 0) acc += __expf(d * TEMP_INV);
    }
    asm volatile("cp.async.wait_group 0;\n");   // drain before exit

    // combine the 4 row-groups (acc lives in lanes with pos==0)
    acc += __shfl_xor_sync(0xffffffffu, acc, 8);
    acc += __shfl_xor_sync(0xffffffffu, acc, 16);

    if (lane == 0) s[wid] = acc;
    __syncthreads();
    if (tid == 0) {
        float d1 = s[0] + s[1] + s[2] + s[3];
        float d2 = s[4] + s[5] + s[6] + s[7];
        out[b] = logf(d1) - logf(d2);
    }
}

extern "C" void kernel_launch(void* const* d_in, const int* in_sizes, int n_in,
                              void* d_out, int out_size) {
    const float* codes = (const float*)d_in[0];
    const float* bank  = (const float*)d_in[1];
    const void*  ibg   = d_in[2];
    const void*  icl   = d_in[3];
    float* out = (float*)d_out;

    const int B = out_size;                 // 1024
    const int K = in_sizes[2] / B;          // 200

    la_loss_kernel<<<B, 256>>>(codes, bank, ibg, icl, out, K);
}

// round 10
// speedup vs baseline: 1.4139x; 1.4139x over previous
#include <cuda_runtime.h>
#include <cuda_bf16.h>

#define DIM 128
#define TEMP_INV (1.0f / 0.07f)
#define STAGES 6

// Cross-block combine scratch (zero-initialized at module load; counters are
// restored to 0 by the consuming block each run -> graph-replay safe).
__device__ float g_dens[2][1024];
__device__ int   g_cnt[1024];

__device__ __forceinline__ float dot4(float4 a, float4 b) {
    return a.x * b.x + a.y * b.y + a.z * b.z + a.w * b.w;
}

__global__ __launch_bounds__(128, 16)
void la_loss_kernel(const float* __restrict__ codes,
                    const float* __restrict__ bank,
                    const void* __restrict__ idx_bg,
                    const void* __restrict__ idx_cl,
                    float* __restrict__ out,
                    int K)
{
    // per-warp private ring buffers: 4 warps x 6 stages x 512B = 12KB
    __shared__ float4 buf[4][STAGES][32];
    __shared__ float s[4];

    const int b    = blockIdx.x >> 1;    // batch item
    const int half = blockIdx.x & 1;     // 0 = background, 1 = close
    const int tid  = threadIdx.x;
    const int wid  = tid >> 5;           // 0..3
    const int lane = tid & 31;

    const void* idx = half ? idx_cl : idx_bg;
    const unsigned int* w32 = (const unsigned int*)idx;

    // ---- per-warp inline dtype detection: values < 2^20, so little-endian
    // int64 => all odd 32-bit words zero. int32 => random words; P(all 0) ~ 0.
    const bool is64 = __all_sync(0xffffffffu, w32[2 * lane + 1] == 0u);

    // ---- load this item's code vector and normalize (per-warp) ----
    float4 c4 = reinterpret_cast<const float4*>(codes + (size_t)b * DIM)[lane];
    float ss = dot4(c4, c4);
#pragma unroll
    for (int o = 16; o; o >>= 1) ss += __shfl_xor_sync(0xffffffffu, ss, o);
    const float rn = rsqrtf(ss);
    const float4 v4 = make_float4(c4.x * rn, c4.y * rn, c4.z * rn, c4.w * rn);

    const int wsub = wid;                       // 4 warps stride the K indices
    const size_t base = (size_t)b * (size_t)K;
    const int F = (K - wsub + 3) >> 2;          // rows this warp owns

    // 32-bit index fetch for both dtypes (low word only; indices >= 0, < 2^20)
    const size_t ibase = is64 ? 2 * base : base;
    const int    istep = is64 ? 2 : 1;
    const char* __restrict__ bank_c = (const char*)bank;

    // fill row f into ring slot; empty commit keeps group accounting uniform
    auto fill = [&](int f, int slot) {
        if (f < F) {
            int m = wsub + 4 * f;
            unsigned ii = w32[ibase + (size_t)(istep * m)];
            const char* src = bank_c + ((size_t)ii * 512u + (unsigned)lane * 16u);
            unsigned sad = (unsigned)__cvta_generic_to_shared(&buf[wid][slot][lane]);
            asm volatile("cp.async.cg.shared.global [%0], [%1], 16;\n"
                         :: "r"(sad), "l"(src));
        }
        asm volatile("cp.async.commit_group;\n");
    };

    // prologue: fill all 6 stages
#pragma unroll
    for (int f = 0; f < STAGES; f++) fill(f, f);

    float acc = 0.0f;
    int slot = 0;
    for (int t = 0; t < F; t++) {
        // oldest of the 6 pending groups (row t) is complete
        asm volatile("cp.async.wait_group %0;\n" :: "n"(STAGES - 1));
        float4 r = buf[wid][slot][lane];   // each lane reads the 16B it filled

        fill(t + STAGES, slot);            // refill with row t+6
        if (++slot == STAGES) slot = 0;

        float d = dot4(r, v4);
#pragma unroll
        for (int o = 16; o; o >>= 1) d += __shfl_xor_sync(0xffffffffu, d, o);
        acc += __expf(d * TEMP_INV);
    }
    asm volatile("cp.async.wait_group 0;\n");   // drain before exit

    if (lane == 0) s[wid] = acc;
    __syncthreads();
    if (tid == 0) {
        float dens = s[0] + s[1] + s[2] + s[3];
        g_dens[half][b] = dens;
        __threadfence();
        int old = atomicAdd(&g_cnt[b], 1);
        if (old == 1) {
            __threadfence();                    // order the peer's store
            float other = g_dens[half ^ 1][b];
            float d1 = half ? other : dens;     // background density
            float d2 = half ? dens : other;     // close density
            out[b] = logf(d1) - logf(d2);
            g_cnt[b] = 0;                       // restore for next replay
        }
    }
}

extern "C" void kernel_launch(void* const* d_in, const int* in_sizes, int n_in,
                              void* d_out, int out_size) {
    const float* codes = (const float*)d_in[0];
    const float* bank  = (const float*)d_in[1];
    const void*  ibg   = d_in[2];
    const void*  icl   = d_in[3];
    float* out = (float*)d_out;

    const int B = out_size;                 // 1024
    const int K = in_sizes[2] / B;          // 200

    la_loss_kernel<<<2 * B, 128>>>(codes, bank, ibg, icl, out, K);
}

// round 14
// speedup vs baseline: 1.5412x; 1.0901x over previous
#include <cuda_runtime.h>
#include <cuda_bf16.h>

#define DIM 128
#define TEMP_INV (1.0f / 0.07f)
#define STAGES 6

__device__ __forceinline__ float dot4(float4 a, float4 b) {
    return a.x * b.x + a.y * b.y + a.z * b.z + a.w * b.w;
}

__global__ __launch_bounds__(256, 8)
void la_loss_kernel(const float* __restrict__ codes,
                    const float* __restrict__ bank,
                    const void* __restrict__ idx_bg,
                    const void* __restrict__ idx_cl,
                    float* __restrict__ out,
                    int K)
{
    // per-warp private ring buffers: 8 warps x 6 stages x 512B = 24KB
    __shared__ float4 buf[8][STAGES][32];
    __shared__ float s[8];

    const int b    = blockIdx.x;
    const int tid  = threadIdx.x;
    const int wid  = tid >> 5;      // 0..7
    const int lane = tid & 31;

    // warps 0-3 -> background indices, warps 4-7 -> close indices
    const void* idx = (wid < 4) ? idx_bg : idx_cl;
    const unsigned int* __restrict__ w32 = (const unsigned int*)idx;

    // ---- per-warp inline index-dtype detection (no extra launch, no sync) ----
    // Index values < 2^20. If little-endian int64, all odd 32-bit words are 0.
    // If int32, those words are random indices; P(32 all zero) ~ 0.
    const bool is64 = __all_sync(0xffffffffu, w32[2 * lane + 1] == 0u);

    // ---- load this batch row's code vector and normalize (per-warp) ----
    float4 c4 = reinterpret_cast<const float4*>(codes + (size_t)b * DIM)[lane];
    float ss = dot4(c4, c4);
#pragma unroll
    for (int o = 16; o; o >>= 1) ss += __shfl_xor_sync(0xffffffffu, ss, o);
    const float rn = rsqrtf(ss);
    const float4 v4 = make_float4(c4.x * rn, c4.y * rn, c4.z * rn, c4.w * rn);

    const int wsub = wid & 3;
    const size_t base = (size_t)b * (size_t)K;
    const int F = (K - wsub + 3) >> 2;   // rows (fills) this warp owns

    // 32-bit index fetch for both dtypes (low word only; indices in [0, 2^20))
    const unsigned int* __restrict__ ip =
        w32 + (is64 ? 2 * base : base) + (is64 ? 2 * wsub : wsub);
    const int istep = is64 ? 8 : 4;      // stride between this warp's rows
    const char* __restrict__ bank_c = (const char*)bank;
    const unsigned lane16 = (unsigned)lane * 16u;

    // fill row f into ring slot; empty commit past the end keeps group
    // accounting uniform (empty groups complete immediately).
    auto fill = [&](int f, int slot) {
        if (f < F) {
            unsigned ii = ip[(size_t)f * istep];
            const char* src = bank_c + ((size_t)ii * 512u + lane16);
            unsigned sad = (unsigned)__cvta_generic_to_shared(&buf[wid][slot][lane]);
            asm volatile("cp.async.cg.shared.global [%0], [%1], 16;\n"
                         :: "r"(sad), "l"(src));
        }
        asm volatile("cp.async.commit_group;\n");
    };

    // prologue: fill all 6 stages (groups for f=0..5 pending)
#pragma unroll
    for (int f = 0; f < STAGES; f++) fill(f, f);

    float acc = 0.0f;
    int slot = 0;
    for (int t = 0; t < F; t++) {
        // oldest of the 6 pending groups (row t) is complete
        asm volatile("cp.async.wait_group %0;\n" :: "n"(STAGES - 1));
        float4 r = buf[wid][slot][lane];   // each lane reads the 16B it filled

        // refill this slot with row t+6 (or empty group past the end)
        fill(t + STAGES, slot);
        if (++slot == STAGES) slot = 0;

        float d = dot4(r, v4);
#pragma unroll
        for (int o = 16; o; o >>= 1) d += __shfl_xor_sync(0xffffffffu, d, o);
        acc += __expf(d * TEMP_INV);
    }
    asm volatile("cp.async.wait_group 0;\n");   // drain before exit

    if (lane == 0) s[wid] = acc;
    __syncthreads();
    if (tid == 0) {
        float d1 = s[0] + s[1] + s[2] + s[3];
        float d2 = s[4] + s[5] + s[6] + s[7];
        out[b] = logf(d1) - logf(d2);
    }
}

extern "C" void kernel_launch(void* const* d_in, const int* in_sizes, int n_in,
                              void* d_out, int out_size) {
    const float* codes = (const float*)d_in[0];
    const float* bank  = (const float*)d_in[1];
    const void*  ibg   = d_in[2];
    const void*  icl   = d_in[3];
    float* out = (float*)d_out;

    const int B = out_size;                 // 1024
    const int K = in_sizes[2] / B;          // 200

    la_loss_kernel<<<B, 256>>>(codes, bank, ibg, icl, out, K);
}

// round 15
// speedup vs baseline: 1.5451x; 1.0026x over previous
#include <cuda_runtime.h>
#include <cuda_bf16.h>

#define DIM 128
#define TEMP_INV (1.0f / 0.07f)
#define STAGES 6

__device__ __forceinline__ float dot4(float4 a, float4 b) {
    return a.x * b.x + a.y * b.y + a.z * b.z + a.w * b.w;
}

__global__ __launch_bounds__(256, 8)
void la_loss_kernel(const float* __restrict__ codes,
                    const float* __restrict__ bank,
                    const void* __restrict__ idx_bg,
                    const void* __restrict__ idx_cl,
                    float* __restrict__ out,
                    int K)
{
    // per-warp private ring buffers: 8 warps x 6 stages x 512B = 24KB
    __shared__ float4 buf[8][STAGES][32];
    __shared__ float s[8];

    const int b    = blockIdx.x;
    const int tid  = threadIdx.x;
    const int wid  = tid >> 5;      // 0..7
    const int lane = tid & 31;

    // warps 0-3 -> background indices, warps 4-7 -> close indices
    const void* idx = (wid < 4) ? idx_bg : idx_cl;

    // ---- per-warp inline index-dtype detection (no extra launch, no sync) ----
    // Index values < 2^20. If little-endian int64, all odd 32-bit words are 0.
    // If int32, those words are random indices; P(32 all zero) ~ 0.
    const unsigned int* w = (const unsigned int*)idx;
    const bool is64 = __all_sync(0xffffffffu, w[2 * lane + 1] == 0u);

    // ---- load this batch row's code vector and normalize (per-warp) ----
    float4 c4 = reinterpret_cast<const float4*>(codes + (size_t)b * DIM)[lane];
    float ss = dot4(c4, c4);
#pragma unroll
    for (int o = 16; o; o >>= 1) ss += __shfl_xor_sync(0xffffffffu, ss, o);
    const float rn = rsqrtf(ss);
    const float4 v4 = make_float4(c4.x * rn, c4.y * rn, c4.z * rn, c4.w * rn);

    const int wsub = wid & 3;
    const size_t base = (size_t)b * (size_t)K;
    const int F = (K - wsub + 3) >> 2;   // rows (fills) this warp owns

    // fill row f into ring slot; empty commit past the end keeps group
    // accounting uniform (empty groups complete immediately).
    auto fill = [&](int f, int slot) {
        if (f < F) {
            int m = wsub + 4 * f;
            long long ii;
            if (is64) ii = reinterpret_cast<const long long*>(idx)[base + m];
            else      ii = (long long)reinterpret_cast<const int*>(idx)[base + m];
            const float4* src = reinterpret_cast<const float4*>(bank + (size_t)ii * DIM) + lane;
            unsigned sad = (unsigned)__cvta_generic_to_shared(&buf[wid][slot][lane]);
            asm volatile("cp.async.cg.shared.global [%0], [%1], 16;\n"
                         :: "r"(sad), "l"(src));
        }
        asm volatile("cp.async.commit_group;\n");
    };

    // prologue: fill all 6 stages (groups for f=0..5 pending)
#pragma unroll
    for (int f = 0; f < STAGES; f++) fill(f, f);

    float acc = 0.0f;
    int slot = 0;
    for (int t = 0; t < F; t++) {
        // oldest of the 6 pending groups (row t) is complete
        asm volatile("cp.async.wait_group %0;\n" :: "n"(STAGES - 1));
        float4 r = buf[wid][slot][lane];   // each lane reads the 16B it filled

        // refill this slot with row t+6 (or empty group past the end)
        fill(t + STAGES, slot);
        if (++slot == STAGES) slot = 0;

        float d = dot4(r, v4);
#pragma unroll
        for (int o = 16; o; o >>= 1) d += __shfl_xor_sync(0xffffffffu, d, o);
        acc += __expf(d * TEMP_INV);
    }
    asm volatile("cp.async.wait_group 0;\n");   // drain before exit

    if (lane == 0) s[wid] = acc;
    __syncthreads();
    if (tid == 0) {
        float d1 = s[0] + s[1] + s[2] + s[3];
        float d2 = s[4] + s[5] + s[6] + s[7];
        out[b] = logf(d1) - logf(d2);
    }
}

extern "C" void kernel_launch(void* const* d_in, const int* in_sizes, int n_in,
                              void* d_out, int out_size) {
    const float* codes = (const float*)d_in[0];
    const float* bank  = (const float*)d_in[1];
    const void*  ibg   = d_in[2];
    const void*  icl   = d_in[3];
    float* out = (float*)d_out;

    const int B = out_size;                 // 1024
    const int K = in_sizes[2] / B;          // 200

    la_loss_kernel<<<B, 256>>>(codes, bank, ibg, icl, out, K);
}